// round 15
// baseline (speedup 1.0000x reference)
#include <cuda_runtime.h>
#include <math.h>

#define NN 10000
#define DD 128
#define KK 16
#define SS 5
#define EE 320000
#define PP 80000
#define NSTEP 4
#define NSEG (NSTEP * NN)
#define NEDGE (NSTEP * PP)
#define CAP 64
#define LN_EPS 1e-5f
#define NPB 4
#define BT 128
#define LOG2E 1.4426950408889634f

typedef unsigned long long ull;

__device__ __forceinline__ ull fma2(ull a, ull b, ull c) {
    ull d; asm("fma.rn.f32x2 %0, %1, %2, %3;" : "=l"(d) : "l"(a), "l"(b), "l"(c));
    return d;
}
__device__ __forceinline__ ull pack2(float lo, float hi) {
    ull r; asm("mov.b64 %0, {%1,%2};" : "=l"(r) : "f"(lo), "f"(hi)); return r;
}
__device__ __forceinline__ void unpack2(ull v, float& lo, float& hi) {
    asm("mov.b64 {%0,%1}, %2;" : "=f"(lo), "=f"(hi) : "l"(v));
}
__device__ __forceinline__ float softplus_fast(float v) {
    float e = __expf(-fabsf(v));
    return fmaxf(v, 0.0f) + __logf(1.0f + e);
}

// Scratch (no cudaMalloc; __device__ globals start zero-initialized)
__device__ __align__(16) float g_seg[(size_t)NSTEP * NN * DD];
__device__ int  g_cnt[NSEG];                       // zeroed by gather at end of run
__device__ __align__(8) int2 g_bkt[(size_t)NSEG * CAP];

// ---------------------------------------------------------------------------
// place: bucket edges by (step, dst)
// ---------------------------------------------------------------------------
__global__ __launch_bounds__(256) void place_kernel(
    const int* __restrict__ edge_index, const int* __restrict__ edge_type,
    const int* __restrict__ perms)
{
    int idx = blockIdx.x * blockDim.x + threadIdx.x;
    if (idx >= NEDGE) return;
    int e = perms[idx];
    int s = idx / PP;
    int seg = s * NN + edge_index[EE + e];
    int pos = atomicAdd(&g_cnt[seg], 1);
    if (pos < CAP)
        g_bkt[(size_t)seg * CAP + pos] = make_int2(edge_index[e], edge_type[e]);
}

// ---------------------------------------------------------------------------
// gather: one warp per segment; 4-wide unrolled mean of (x[src] + rel[rt])
// ---------------------------------------------------------------------------
__global__ __launch_bounds__(256) void gather_kernel(
    const float* __restrict__ x, const float* __restrict__ rel_table)
{
    int seg  = (blockIdx.x * blockDim.x + threadIdx.x) >> 5;
    int lane = threadIdx.x & 31;
    if (seg >= NSEG) return;
    int cnt = g_cnt[seg];
    int use = min(cnt, CAP);
    const int2* bkt = g_bkt + (size_t)seg * CAP;
    const float4* x4 = (const float4*)x;
    const float4* r4 = (const float4*)rel_table;
    float4 acc = make_float4(0.f, 0.f, 0.f, 0.f);
    int i = 0;
    for (; i + 3 < use; i += 4) {
        int2 e0 = bkt[i], e1 = bkt[i + 1], e2 = bkt[i + 2], e3 = bkt[i + 3];
        float4 a0 = x4[(size_t)e0.x * 32 + lane];
        float4 b0 = r4[(size_t)e0.y * 32 + lane];
        float4 a1 = x4[(size_t)e1.x * 32 + lane];
        float4 b1 = r4[(size_t)e1.y * 32 + lane];
        float4 a2 = x4[(size_t)e2.x * 32 + lane];
        float4 b2 = r4[(size_t)e2.y * 32 + lane];
        float4 a3 = x4[(size_t)e3.x * 32 + lane];
        float4 b3 = r4[(size_t)e3.y * 32 + lane];
        acc.x += (a0.x + b0.x) + (a1.x + b1.x) + (a2.x + b2.x) + (a3.x + b3.x);
        acc.y += (a0.y + b0.y) + (a1.y + b1.y) + (a2.y + b2.y) + (a3.y + b3.y);
        acc.z += (a0.z + b0.z) + (a1.z + b1.z) + (a2.z + b2.z) + (a3.z + b3.z);
        acc.w += (a0.w + b0.w) + (a1.w + b1.w) + (a2.w + b2.w) + (a3.w + b3.w);
    }
    for (; i < use; i++) {
        int2 e0 = bkt[i];
        float4 a0 = x4[(size_t)e0.x * 32 + lane];
        float4 b0 = r4[(size_t)e0.y * 32 + lane];
        acc.x += a0.x + b0.x; acc.y += a0.y + b0.y;
        acc.z += a0.z + b0.z; acc.w += a0.w + b0.w;
    }
    float inv = 1.0f / fmaxf((float)cnt, 1.0f);
    acc.x *= inv; acc.y *= inv; acc.z *= inv; acc.w *= inv;
    ((float4*)g_seg)[(size_t)seg * 32 + lane] = acc;
    if (lane == 0) g_cnt[seg] = 0;   // reset for next graph replay
}

// ---------------------------------------------------------------------------
// Fused per-node layer — R14 structure + merged single-round B/C projection.
// 128 threads, 4 nodes/block, occupancy 6.
// ---------------------------------------------------------------------------
__global__ __launch_bounds__(BT, 6) void node_kernel(
    const float* __restrict__ x,
    const float* __restrict__ log_A,
    const float* __restrict__ W_B,
    const float* __restrict__ W_C,
    const float* __restrict__ W_delta,
    const float* __restrict__ b_delta,
    const float* __restrict__ W_g,
    const float* __restrict__ b_g,
    const float* __restrict__ W_out,
    const float* __restrict__ b_out,
    const float* __restrict__ ln_g,
    const float* __restrict__ ln_b,
    float* __restrict__ out)
{
    __shared__ __align__(16) float tokp[SS][DD][NPB];   // node-minor tokens
    __shared__ __align__(16) float Bs[NPB][SS][KK];
    __shared__ __align__(16) float Cs[NPB][SS][KK];
    __shared__ __align__(16) float scp[DD][NPB];
    __shared__ float rbuf[NPB][4];
    __shared__ float gash[DD][NPB];    // gate linear result

    const int n0 = blockIdx.x * NPB;
    const int t = threadIdx.x;          // = column d

    // ---- build tokens (node-minor layout) ---------------------------------
#pragma unroll
    for (int m = 0; m < NPB; m++) {
        int n = n0 + m;
        tokp[0][t][m] = x[(size_t)n * DD + t];
#pragma unroll
        for (int s = 1; s < SS; s++)
            tokp[s][t][m] = g_seg[((size_t)(s - 1) * NN + n) * DD + t];
    }
    __syncthreads();

    // ---- delta projection + gate projection (merged), f32x2-packed --------
    ull accp[2][SS];
    ull ga01, ga23;
    {
        float bd = b_delta[t];
        ull bd2 = pack2(bd, bd);
#pragma unroll
        for (int s = 0; s < SS; s++) { accp[0][s] = bd2; accp[1][s] = bd2; }
        float bg = b_g[t];
        ga01 = ga23 = pack2(bg, bg);
    }
#pragma unroll 4
    for (int j = 0; j < DD; j++) {
        float w = W_delta[j * DD + t];
        float g = W_g[j * DD + t];
        ull w2 = pack2(w, w);
        ull g2 = pack2(g, g);
        ulonglong2 t0 = *(const ulonglong2*)&tokp[0][j][0];
        accp[0][0] = fma2(t0.x, w2, accp[0][0]);
        accp[1][0] = fma2(t0.y, w2, accp[1][0]);
        ga01 = fma2(t0.x, g2, ga01);
        ga23 = fma2(t0.y, g2, ga23);
#pragma unroll
        for (int s = 1; s < SS; s++) {
            ulonglong2 tv = *(const ulonglong2*)&tokp[s][j][0];
            accp[0][s] = fma2(tv.x, w2, accp[0][s]);
            accp[1][s] = fma2(tv.y, w2, accp[1][s]);
        }
    }
    float del[NPB][SS];
#pragma unroll
    for (int s = 0; s < SS; s++) {
        unpack2(accp[0][s], del[0][s], del[1][s]);
        unpack2(accp[1][s], del[2][s], del[3][s]);
    }
#pragma unroll
    for (int m = 0; m < NPB; m++)
#pragma unroll
        for (int s = 0; s < SS; s++)
            del[m][s] = softplus_fast(del[m][s]);
    {   // stash gate linear (pre-silu) in smem; applied after scan
        float g0, g1, g2v, g3;
        unpack2(ga01, g0, g1); unpack2(ga23, g2v, g3);
        gash[t][0] = g0; gash[t][1] = g1; gash[t][2] = g2v; gash[t][3] = g3;
    }

    // ---- merged B+C projection: 80 tasks, single round --------------------
    if (t < SS * KK) {
        int s = t / KK, k = t % KK;
        ull b01 = 0ull, b23 = 0ull, c01 = 0ull, c23 = 0ull;
#pragma unroll 4
        for (int j = 0; j < DD; j++) {
            float wb = W_B[j * KK + k];
            float wc = W_C[j * KK + k];
            ull wb2 = pack2(wb, wb);
            ull wc2 = pack2(wc, wc);
            ulonglong2 tv = *(const ulonglong2*)&tokp[s][j][0];
            b01 = fma2(tv.x, wb2, b01);
            b23 = fma2(tv.y, wb2, b23);
            c01 = fma2(tv.x, wc2, c01);
            c23 = fma2(tv.y, wc2, c23);
        }
        float v0, v1, v2, v3;
        unpack2(b01, v0, v1); unpack2(b23, v2, v3);
        Bs[0][s][k] = v0; Bs[1][s][k] = v1;
        Bs[2][s][k] = v2; Bs[3][s][k] = v3;
        unpack2(c01, v0, v1); unpack2(c23, v2, v3);
        Cs[0][s][k] = v0; Cs[1][s][k] = v1;
        Cs[2][s][k] = v2; Cs[3][s][k] = v3;
    }
    __syncthreads();

    // ---- single-pass bidirectional scan, k halves of 8, exp2-folded -------
    const int d = t;
    float ysb[NPB];
#pragma unroll
    for (int m = 0; m < NPB; m++) ysb[m] = 0.f;

#pragma unroll
    for (int half = 0; half < 2; half++) {
        float ac[8];
        {
            const float4* la = (const float4*)(log_A + d * KK + half * 8);
#pragma unroll
            for (int q = 0; q < 2; q++) {
                float4 v = la[q];
                ac[q * 4 + 0] = -LOG2E * __expf(v.x);
                ac[q * 4 + 1] = -LOG2E * __expf(v.y);
                ac[q * 4 + 2] = -LOG2E * __expf(v.z);
                ac[q * 4 + 3] = -LOG2E * __expf(v.w);
            }
        }
#pragma unroll
        for (int m = 0; m < NPB; m++) {
            float F[8], Dv[8], ap[8];
#pragma unroll
            for (int k = 0; k < 8; k++) { F[k] = 0.f; Dv[k] = 0.f; ap[k] = 0.f; }
            float ys = 0.f, yb = 0.f;
            const float4* Bp = (const float4*)&Bs[m][0][0];
            const float4* Cp = (const float4*)&Cs[m][0][0];
#pragma unroll
            for (int s = 0; s < SS; s++) {
                float dl = del[m][s];
                float dx = dl * tokp[s][d][m];
#pragma unroll
                for (int q = 0; q < 2; q++) {
                    float4 Bv = Bp[s * 4 + half * 2 + q];
                    float4 Cv = Cp[s * 4 + half * 2 + q];
#pragma unroll
                    for (int e = 0; e < 4; e++) {
                        int k = q * 4 + e;
                        float Be = (e == 0) ? Bv.x : (e == 1) ? Bv.y : (e == 2) ? Bv.z : Bv.w;
                        float Ce = (e == 0) ? Cv.x : (e == 1) ? Cv.y : (e == 2) ? Cv.z : Cv.w;
                        float a  = exp2f(dl * ac[k]);
                        float bx = dx * Be;
                        F[k]  = fmaf(a, F[k], bx);
                        ys    = fmaf(Ce, F[k], ys);
                        Dv[k] = fmaf(ap[k], Dv[k], Ce);
                        yb    = fmaf(bx, Dv[k], yb);
                        ap[k] = a;
                    }
                }
            }
            ysb[m] += ys + yb;
        }
    }
#pragma unroll
    for (int m = 0; m < NPB; m++)
        scp[d][m] = ysb[m] * (1.0f / SS);
    __syncthreads();

    // ---- out projection, f32x2-packed -------------------------------------
    ull oa01, oa23;
    {
        float bo = b_out[d];
        oa01 = oa23 = pack2(bo, bo);
    }
#pragma unroll 8
    for (int j = 0; j < DD; j++) {
        float o = W_out[j * DD + d];
        ull o2 = pack2(o, o);
        ulonglong2 sv = *(const ulonglong2*)&scp[j][0];
        oa01 = fma2(sv.x, o2, oa01);
        oa23 = fma2(sv.y, o2, oa23);
    }
    float res[NPB];
    {
        float oa[NPB];
        unpack2(oa01, oa[0], oa[1]); unpack2(oa23, oa[2], oa[3]);
#pragma unroll
        for (int m = 0; m < NPB; m++) {
            float gl = gash[d][m];
            float gate = gl / (1.0f + __expf(-gl));
            res[m] = tokp[0][d][m] + gate * oa[m];
        }
    }

    // ---- LayerNorm --------------------------------------------------------
    {
        float v[NPB];
#pragma unroll
        for (int m = 0; m < NPB; m++) v[m] = res[m];
#pragma unroll
        for (int o = 16; o; o >>= 1)
#pragma unroll
            for (int m = 0; m < NPB; m++)
                v[m] += __shfl_xor_sync(0xffffffffu, v[m], o);
        if ((t & 31) == 0)
#pragma unroll
            for (int m = 0; m < NPB; m++) rbuf[m][t >> 5] = v[m];
    }
    __syncthreads();
    float mean[NPB];
#pragma unroll
    for (int m = 0; m < NPB; m++)
        mean[m] = (rbuf[m][0] + rbuf[m][1] + rbuf[m][2] + rbuf[m][3]) * (1.0f / DD);
    __syncthreads();
    {
        float v[NPB];
#pragma unroll
        for (int m = 0; m < NPB; m++) {
            float c = res[m] - mean[m];
            v[m] = c * c;
        }
#pragma unroll
        for (int o = 16; o; o >>= 1)
#pragma unroll
            for (int m = 0; m < NPB; m++)
                v[m] += __shfl_xor_sync(0xffffffffu, v[m], o);
        if ((t & 31) == 0)
#pragma unroll
            for (int m = 0; m < NPB; m++) rbuf[m][t >> 5] = v[m];
    }
    __syncthreads();
    {
        float lg = ln_g[t], lb = ln_b[t];
#pragma unroll
        for (int m = 0; m < NPB; m++) {
            float var = (rbuf[m][0] + rbuf[m][1] + rbuf[m][2] + rbuf[m][3]) * (1.0f / DD);
            float c = res[m] - mean[m];
            out[(size_t)(n0 + m) * DD + t] = c * rsqrtf(var + LN_EPS) * lg + lb;
        }
    }
}

// ---------------------------------------------------------------------------
extern "C" void kernel_launch(void* const* d_in, const int* in_sizes, int n_in,
                              void* d_out, int out_size)
{
    const float* x          = (const float*)d_in[0];
    const int*   edge_index = (const int*)  d_in[1];
    const int*   edge_type  = (const int*)  d_in[2];
    const int*   perms      = (const int*)  d_in[3];
    const float* rel_table  = (const float*)d_in[4];
    const float* log_A      = (const float*)d_in[5];
    const float* W_B        = (const float*)d_in[6];
    const float* W_C        = (const float*)d_in[7];
    const float* W_delta    = (const float*)d_in[8];
    const float* b_delta    = (const float*)d_in[9];
    const float* W_g        = (const float*)d_in[10];
    const float* b_g        = (const float*)d_in[11];
    const float* W_out      = (const float*)d_in[12];
    const float* b_out      = (const float*)d_in[13];
    const float* ln_g       = (const float*)d_in[14];
    const float* ln_b       = (const float*)d_in[15];
    float* out = (float*)d_out;

    place_kernel<<<(NEDGE + 255) / 256, 256>>>(edge_index, edge_type, perms);
    gather_kernel<<<(NSEG * 32 + 255) / 256, 256>>>(x, rel_table);
    node_kernel<<<NN / NPB, BT>>>(x, log_A, W_B, W_C, W_delta, b_delta,
                                  W_g, b_g, W_out, b_out, ln_g, ln_b, out);
}

// round 16
// speedup vs baseline: 1.5290x; 1.5290x over previous
#include <cuda_runtime.h>
#include <math.h>

#define NN 10000
#define DD 128
#define KK 16
#define SS 5
#define EE 320000
#define PP 80000
#define NSTEP 4
#define NSEG (NSTEP * NN)
#define NEDGE (NSTEP * PP)
#define CAP 64
#define LN_EPS 1e-5f
#define NPB 4
#define BT 128
#define LOG2E 1.4426950408889634f

typedef unsigned long long ull;

__device__ __forceinline__ ull fma2(ull a, ull b, ull c) {
    ull d; asm("fma.rn.f32x2 %0, %1, %2, %3;" : "=l"(d) : "l"(a), "l"(b), "l"(c));
    return d;
}
__device__ __forceinline__ ull pack2(float lo, float hi) {
    ull r; asm("mov.b64 %0, {%1,%2};" : "=l"(r) : "f"(lo), "f"(hi)); return r;
}
__device__ __forceinline__ void unpack2(ull v, float& lo, float& hi) {
    asm("mov.b64 {%0,%1}, %2;" : "=f"(lo), "=f"(hi) : "l"(v));
}
__device__ __forceinline__ float softplus_fast(float v) {
    float e = __expf(-fabsf(v));
    return fmaxf(v, 0.0f) + __logf(1.0f + e);
}

// Scratch (no cudaMalloc; __device__ globals start zero-initialized)
__device__ __align__(16) float g_seg[(size_t)NSTEP * NN * DD];
__device__ int  g_cnt[NSEG];                       // zeroed by gather at end of run
__device__ __align__(8) int2 g_bkt[(size_t)NSEG * CAP];

// ---------------------------------------------------------------------------
// place: bucket edges by (step, dst)
// ---------------------------------------------------------------------------
__global__ __launch_bounds__(256) void place_kernel(
    const int* __restrict__ edge_index, const int* __restrict__ edge_type,
    const int* __restrict__ perms)
{
    int idx = blockIdx.x * blockDim.x + threadIdx.x;
    if (idx >= NEDGE) return;
    int e = perms[idx];
    int s = idx / PP;
    int seg = s * NN + edge_index[EE + e];
    int pos = atomicAdd(&g_cnt[seg], 1);
    if (pos < CAP)
        g_bkt[(size_t)seg * CAP + pos] = make_int2(edge_index[e], edge_type[e]);
}

// ---------------------------------------------------------------------------
// gather: one warp per segment; 4-wide unrolled mean of (x[src] + rel[rt])
// ---------------------------------------------------------------------------
__global__ __launch_bounds__(256) void gather_kernel(
    const float* __restrict__ x, const float* __restrict__ rel_table)
{
    int seg  = (blockIdx.x * blockDim.x + threadIdx.x) >> 5;
    int lane = threadIdx.x & 31;
    if (seg >= NSEG) return;
    int cnt = g_cnt[seg];
    int use = min(cnt, CAP);
    const int2* bkt = g_bkt + (size_t)seg * CAP;
    const float4* x4 = (const float4*)x;
    const float4* r4 = (const float4*)rel_table;
    float4 acc = make_float4(0.f, 0.f, 0.f, 0.f);
    int i = 0;
    for (; i + 3 < use; i += 4) {
        int2 e0 = bkt[i], e1 = bkt[i + 1], e2 = bkt[i + 2], e3 = bkt[i + 3];
        float4 a0 = x4[(size_t)e0.x * 32 + lane];
        float4 b0 = r4[(size_t)e0.y * 32 + lane];
        float4 a1 = x4[(size_t)e1.x * 32 + lane];
        float4 b1 = r4[(size_t)e1.y * 32 + lane];
        float4 a2 = x4[(size_t)e2.x * 32 + lane];
        float4 b2 = r4[(size_t)e2.y * 32 + lane];
        float4 a3 = x4[(size_t)e3.x * 32 + lane];
        float4 b3 = r4[(size_t)e3.y * 32 + lane];
        acc.x += (a0.x + b0.x) + (a1.x + b1.x) + (a2.x + b2.x) + (a3.x + b3.x);
        acc.y += (a0.y + b0.y) + (a1.y + b1.y) + (a2.y + b2.y) + (a3.y + b3.y);
        acc.z += (a0.z + b0.z) + (a1.z + b1.z) + (a2.z + b2.z) + (a3.z + b3.z);
        acc.w += (a0.w + b0.w) + (a1.w + b1.w) + (a2.w + b2.w) + (a3.w + b3.w);
    }
    for (; i < use; i++) {
        int2 e0 = bkt[i];
        float4 a0 = x4[(size_t)e0.x * 32 + lane];
        float4 b0 = r4[(size_t)e0.y * 32 + lane];
        acc.x += a0.x + b0.x; acc.y += a0.y + b0.y;
        acc.z += a0.z + b0.z; acc.w += a0.w + b0.w;
    }
    float inv = 1.0f / fmaxf((float)cnt, 1.0f);
    acc.x *= inv; acc.y *= inv; acc.z *= inv; acc.w *= inv;
    ((float4*)g_seg)[(size_t)seg * 32 + lane] = acc;
    if (lane == 0) g_cnt[seg] = 0;   // reset for next graph replay
}

// ---------------------------------------------------------------------------
// Fused per-node layer — R9 structure (proven) + exp2-folded scan.
// 128 threads, 4 nodes/block, occupancy 6.
// ---------------------------------------------------------------------------
__global__ __launch_bounds__(BT, 6) void node_kernel(
    const float* __restrict__ x,
    const float* __restrict__ log_A,
    const float* __restrict__ W_B,
    const float* __restrict__ W_C,
    const float* __restrict__ W_delta,
    const float* __restrict__ b_delta,
    const float* __restrict__ W_g,
    const float* __restrict__ b_g,
    const float* __restrict__ W_out,
    const float* __restrict__ b_out,
    const float* __restrict__ ln_g,
    const float* __restrict__ ln_b,
    float* __restrict__ out)
{
    __shared__ __align__(16) float tokp[SS][DD][NPB];   // node-minor tokens
    __shared__ __align__(16) float Bs[NPB][SS][KK];
    __shared__ __align__(16) float Cs[NPB][SS][KK];
    __shared__ __align__(16) float scp[DD][NPB];
    __shared__ float rbuf[NPB][4];
    __shared__ float gash[DD][NPB];    // gate linear result

    const int n0 = blockIdx.x * NPB;
    const int t = threadIdx.x;          // = column d

    // ---- build tokens (node-minor layout) ---------------------------------
#pragma unroll
    for (int m = 0; m < NPB; m++) {
        int n = n0 + m;
        tokp[0][t][m] = x[(size_t)n * DD + t];
#pragma unroll
        for (int s = 1; s < SS; s++)
            tokp[s][t][m] = g_seg[((size_t)(s - 1) * NN + n) * DD + t];
    }
    __syncthreads();

    // ---- delta projection + gate projection (merged), f32x2-packed --------
    ull accp[2][SS];
    ull ga01, ga23;
    {
        float bd = b_delta[t];
        ull bd2 = pack2(bd, bd);
#pragma unroll
        for (int s = 0; s < SS; s++) { accp[0][s] = bd2; accp[1][s] = bd2; }
        float bg = b_g[t];
        ga01 = ga23 = pack2(bg, bg);
    }
#pragma unroll 4
    for (int j = 0; j < DD; j++) {
        float w = W_delta[j * DD + t];
        float g = W_g[j * DD + t];
        ull w2 = pack2(w, w);
        ull g2 = pack2(g, g);
        ulonglong2 t0 = *(const ulonglong2*)&tokp[0][j][0];
        accp[0][0] = fma2(t0.x, w2, accp[0][0]);
        accp[1][0] = fma2(t0.y, w2, accp[1][0]);
        ga01 = fma2(t0.x, g2, ga01);
        ga23 = fma2(t0.y, g2, ga23);
#pragma unroll
        for (int s = 1; s < SS; s++) {
            ulonglong2 tv = *(const ulonglong2*)&tokp[s][j][0];
            accp[0][s] = fma2(tv.x, w2, accp[0][s]);
            accp[1][s] = fma2(tv.y, w2, accp[1][s]);
        }
    }
    float del[NPB][SS];
#pragma unroll
    for (int s = 0; s < SS; s++) {
        unpack2(accp[0][s], del[0][s], del[1][s]);
        unpack2(accp[1][s], del[2][s], del[3][s]);
    }
#pragma unroll
    for (int m = 0; m < NPB; m++)
#pragma unroll
        for (int s = 0; s < SS; s++)
            del[m][s] = softplus_fast(del[m][s]);
    {   // stash gate linear (pre-silu) in smem; applied after scan
        float g0, g1, g2v, g3;
        unpack2(ga01, g0, g1); unpack2(ga23, g2v, g3);
        gash[t][0] = g0; gash[t][1] = g1; gash[t][2] = g2v; gash[t][3] = g3;
    }

    // ---- B/C projections: 160 cooperative tasks, f32x2-packed -------------
    for (int task = t; task < 2 * SS * KK; task += BT) {
        int which = task / (SS * KK);
        int r = task % (SS * KK);
        int s = r / KK, k = r % KK;
        const float* W = which ? W_C : W_B;
        ull a01 = 0ull, a23 = 0ull;
#pragma unroll 4
        for (int j = 0; j < DD; j++) {
            float w = W[j * KK + k];
            ull w2 = pack2(w, w);
            ulonglong2 tv = *(const ulonglong2*)&tokp[s][j][0];
            a01 = fma2(tv.x, w2, a01);
            a23 = fma2(tv.y, w2, a23);
        }
        float v0, v1, v2, v3;
        unpack2(a01, v0, v1);
        unpack2(a23, v2, v3);
        float* dst = which ? &Cs[0][s][k] : &Bs[0][s][k];
        dst[0 * SS * KK] = v0; dst[1 * SS * KK] = v1;
        dst[2 * SS * KK] = v2; dst[3 * SS * KK] = v3;
    }
    __syncthreads();

    // ---- single-pass bidirectional scan, k halves of 8, exp2-folded -------
    const int d = t;
    float ysb[NPB];
#pragma unroll
    for (int m = 0; m < NPB; m++) ysb[m] = 0.f;

#pragma unroll
    for (int half = 0; half < 2; half++) {
        float ac[8];
        {
            const float4* la = (const float4*)(log_A + d * KK + half * 8);
#pragma unroll
            for (int q = 0; q < 2; q++) {
                float4 v = la[q];
                ac[q * 4 + 0] = -LOG2E * __expf(v.x);
                ac[q * 4 + 1] = -LOG2E * __expf(v.y);
                ac[q * 4 + 2] = -LOG2E * __expf(v.z);
                ac[q * 4 + 3] = -LOG2E * __expf(v.w);
            }
        }
#pragma unroll
        for (int m = 0; m < NPB; m++) {
            float F[8], Dv[8], ap[8];
#pragma unroll
            for (int k = 0; k < 8; k++) { F[k] = 0.f; Dv[k] = 0.f; ap[k] = 0.f; }
            float ys = 0.f, yb = 0.f;
            const float4* Bp = (const float4*)&Bs[m][0][0];
            const float4* Cp = (const float4*)&Cs[m][0][0];
#pragma unroll
            for (int s = 0; s < SS; s++) {
                float dl = del[m][s];
                float dx = dl * tokp[s][d][m];
#pragma unroll
                for (int q = 0; q < 2; q++) {
                    float4 Bv = Bp[s * 4 + half * 2 + q];
                    float4 Cv = Cp[s * 4 + half * 2 + q];
#pragma unroll
                    for (int e = 0; e < 4; e++) {
                        int k = q * 4 + e;
                        float Be = (e == 0) ? Bv.x : (e == 1) ? Bv.y : (e == 2) ? Bv.z : Bv.w;
                        float Ce = (e == 0) ? Cv.x : (e == 1) ? Cv.y : (e == 2) ? Cv.z : Cv.w;
                        float a  = exp2f(dl * ac[k]);
                        float bx = dx * Be;
                        F[k]  = fmaf(a, F[k], bx);
                        ys    = fmaf(Ce, F[k], ys);
                        Dv[k] = fmaf(ap[k], Dv[k], Ce);
                        yb    = fmaf(bx, Dv[k], yb);
                        ap[k] = a;
                    }
                }
            }
            ysb[m] += ys + yb;
        }
    }
#pragma unroll
    for (int m = 0; m < NPB; m++)
        scp[d][m] = ysb[m] * (1.0f / SS);
    __syncthreads();

    // ---- out projection, f32x2-packed -------------------------------------
    ull oa01, oa23;
    {
        float bo = b_out[d];
        oa01 = oa23 = pack2(bo, bo);
    }
#pragma unroll 8
    for (int j = 0; j < DD; j++) {
        float o = W_out[j * DD + d];
        ull o2 = pack2(o, o);
        ulonglong2 sv = *(const ulonglong2*)&scp[j][0];
        oa01 = fma2(sv.x, o2, oa01);
        oa23 = fma2(sv.y, o2, oa23);
    }
    float res[NPB];
    {
        float oa[NPB];
        unpack2(oa01, oa[0], oa[1]); unpack2(oa23, oa[2], oa[3]);
#pragma unroll
        for (int m = 0; m < NPB; m++) {
            float gl = gash[d][m];
            float gate = gl / (1.0f + __expf(-gl));
            res[m] = tokp[0][d][m] + gate * oa[m];
        }
    }

    // ---- LayerNorm --------------------------------------------------------
    {
        float v[NPB];
#pragma unroll
        for (int m = 0; m < NPB; m++) v[m] = res[m];
#pragma unroll
        for (int o = 16; o; o >>= 1)
#pragma unroll
            for (int m = 0; m < NPB; m++)
                v[m] += __shfl_xor_sync(0xffffffffu, v[m], o);
        if ((t & 31) == 0)
#pragma unroll
            for (int m = 0; m < NPB; m++) rbuf[m][t >> 5] = v[m];
    }
    __syncthreads();
    float mean[NPB];
#pragma unroll
    for (int m = 0; m < NPB; m++)
        mean[m] = (rbuf[m][0] + rbuf[m][1] + rbuf[m][2] + rbuf[m][3]) * (1.0f / DD);
    __syncthreads();
    {
        float v[NPB];
#pragma unroll
        for (int m = 0; m < NPB; m++) {
            float c = res[m] - mean[m];
            v[m] = c * c;
        }
#pragma unroll
        for (int o = 16; o; o >>= 1)
#pragma unroll
            for (int m = 0; m < NPB; m++)
                v[m] += __shfl_xor_sync(0xffffffffu, v[m], o);
        if ((t & 31) == 0)
#pragma unroll
            for (int m = 0; m < NPB; m++) rbuf[m][t >> 5] = v[m];
    }
    __syncthreads();
    {
        float lg = ln_g[t], lb = ln_b[t];
#pragma unroll
        for (int m = 0; m < NPB; m++) {
            float var = (rbuf[m][0] + rbuf[m][1] + rbuf[m][2] + rbuf[m][3]) * (1.0f / DD);
            float c = res[m] - mean[m];
            out[(size_t)(n0 + m) * DD + t] = c * rsqrtf(var + LN_EPS) * lg + lb;
        }
    }
}

// ---------------------------------------------------------------------------
extern "C" void kernel_launch(void* const* d_in, const int* in_sizes, int n_in,
                              void* d_out, int out_size)
{
    const float* x          = (const float*)d_in[0];
    const int*   edge_index = (const int*)  d_in[1];
    const int*   edge_type  = (const int*)  d_in[2];
    const int*   perms      = (const int*)  d_in[3];
    const float* rel_table  = (const float*)d_in[4];
    const float* log_A      = (const float*)d_in[5];
    const float* W_B        = (const float*)d_in[6];
    const float* W_C        = (const float*)d_in[7];
    const float* W_delta    = (const float*)d_in[8];
    const float* b_delta    = (const float*)d_in[9];
    const float* W_g        = (const float*)d_in[10];
    const float* b_g        = (const float*)d_in[11];
    const float* W_out      = (const float*)d_in[12];
    const float* b_out      = (const float*)d_in[13];
    const float* ln_g       = (const float*)d_in[14];
    const float* ln_b       = (const float*)d_in[15];
    float* out = (float*)d_out;

    place_kernel<<<(NEDGE + 255) / 256, 256>>>(edge_index, edge_type, perms);
    gather_kernel<<<(NSEG * 32 + 255) / 256, 256>>>(x, rel_table);
    node_kernel<<<NN / NPB, BT>>>(x, log_A, W_B, W_C, W_delta, b_delta,
                                  W_g, b_g, W_out, b_out, ln_g, ln_b, out);
}

// round 17
// speedup vs baseline: 1.5576x; 1.0187x over previous
#include <cuda_runtime.h>
#include <math.h>

#define NN 10000
#define DD 128
#define KK 16
#define SS 5
#define EE 320000
#define PP 80000
#define NSTEP 4
#define NSEG (NSTEP * NN)
#define NEDGE (NSTEP * PP)
#define CAP 64
#define LN_EPS 1e-5f
#define NPB 4
#define BT 128
#define LOG2E 1.4426950408889634f

typedef unsigned long long ull;

__device__ __forceinline__ ull fma2(ull a, ull b, ull c) {
    ull d; asm("fma.rn.f32x2 %0, %1, %2, %3;" : "=l"(d) : "l"(a), "l"(b), "l"(c));
    return d;
}
__device__ __forceinline__ ull pack2(float lo, float hi) {
    ull r; asm("mov.b64 %0, {%1,%2};" : "=l"(r) : "f"(lo), "f"(hi)); return r;
}
__device__ __forceinline__ void unpack2(ull v, float& lo, float& hi) {
    asm("mov.b64 {%0,%1}, %2;" : "=f"(lo), "=f"(hi) : "l"(v));
}
__device__ __forceinline__ float softplus_fast(float v) {
    float e = __expf(-fabsf(v));
    return fmaxf(v, 0.0f) + __logf(1.0f + e);
}

// Scratch (no cudaMalloc; __device__ globals start zero-initialized)
__device__ __align__(16) float g_seg[(size_t)NSTEP * NN * DD];
__device__ int  g_cnt[NSEG];                       // zeroed by gather at end of run
__device__ __align__(8) int2 g_bkt[(size_t)NSEG * CAP];

// ---------------------------------------------------------------------------
// place: bucket edges by (step, dst)
// ---------------------------------------------------------------------------
__global__ __launch_bounds__(256) void place_kernel(
    const int* __restrict__ edge_index, const int* __restrict__ edge_type,
    const int* __restrict__ perms)
{
    int idx = blockIdx.x * blockDim.x + threadIdx.x;
    if (idx >= NEDGE) return;
    int e = perms[idx];
    int s = idx / PP;
    int seg = s * NN + edge_index[EE + e];
    int pos = atomicAdd(&g_cnt[seg], 1);
    if (pos < CAP)
        g_bkt[(size_t)seg * CAP + pos] = make_int2(edge_index[e], edge_type[e]);
}

// ---------------------------------------------------------------------------
// gather: one warp per segment; 4-wide unrolled mean of (x[src] + rel[rt])
// ---------------------------------------------------------------------------
__global__ __launch_bounds__(256) void gather_kernel(
    const float* __restrict__ x, const float* __restrict__ rel_table)
{
    int seg  = (blockIdx.x * blockDim.x + threadIdx.x) >> 5;
    int lane = threadIdx.x & 31;
    if (seg >= NSEG) return;
    int cnt = g_cnt[seg];
    int use = min(cnt, CAP);
    const int2* bkt = g_bkt + (size_t)seg * CAP;
    const float4* x4 = (const float4*)x;
    const float4* r4 = (const float4*)rel_table;
    float4 acc = make_float4(0.f, 0.f, 0.f, 0.f);
    int i = 0;
    for (; i + 3 < use; i += 4) {
        int2 e0 = bkt[i], e1 = bkt[i + 1], e2 = bkt[i + 2], e3 = bkt[i + 3];
        float4 a0 = x4[(size_t)e0.x * 32 + lane];
        float4 b0 = r4[(size_t)e0.y * 32 + lane];
        float4 a1 = x4[(size_t)e1.x * 32 + lane];
        float4 b1 = r4[(size_t)e1.y * 32 + lane];
        float4 a2 = x4[(size_t)e2.x * 32 + lane];
        float4 b2 = r4[(size_t)e2.y * 32 + lane];
        float4 a3 = x4[(size_t)e3.x * 32 + lane];
        float4 b3 = r4[(size_t)e3.y * 32 + lane];
        acc.x += (a0.x + b0.x) + (a1.x + b1.x) + (a2.x + b2.x) + (a3.x + b3.x);
        acc.y += (a0.y + b0.y) + (a1.y + b1.y) + (a2.y + b2.y) + (a3.y + b3.y);
        acc.z += (a0.z + b0.z) + (a1.z + b1.z) + (a2.z + b2.z) + (a3.z + b3.z);
        acc.w += (a0.w + b0.w) + (a1.w + b1.w) + (a2.w + b2.w) + (a3.w + b3.w);
    }
    for (; i < use; i++) {
        int2 e0 = bkt[i];
        float4 a0 = x4[(size_t)e0.x * 32 + lane];
        float4 b0 = r4[(size_t)e0.y * 32 + lane];
        acc.x += a0.x + b0.x; acc.y += a0.y + b0.y;
        acc.z += a0.z + b0.z; acc.w += a0.w + b0.w;
    }
    float inv = 1.0f / fmaxf((float)cnt, 1.0f);
    acc.x *= inv; acc.y *= inv; acc.z *= inv; acc.w *= inv;
    ((float4*)g_seg)[(size_t)seg * 32 + lane] = acc;
    if (lane == 0) g_cnt[seg] = 0;   // reset for next graph replay
}

// ---------------------------------------------------------------------------
// Fused per-node layer — R16 structure + merged single-round B/C projection.
// 128 threads, 4 nodes/block, occupancy 6.
// ---------------------------------------------------------------------------
__global__ __launch_bounds__(BT, 6) void node_kernel(
    const float* __restrict__ x,
    const float* __restrict__ log_A,
    const float* __restrict__ W_B,
    const float* __restrict__ W_C,
    const float* __restrict__ W_delta,
    const float* __restrict__ b_delta,
    const float* __restrict__ W_g,
    const float* __restrict__ b_g,
    const float* __restrict__ W_out,
    const float* __restrict__ b_out,
    const float* __restrict__ ln_g,
    const float* __restrict__ ln_b,
    float* __restrict__ out)
{
    __shared__ __align__(16) float tokp[SS][DD][NPB];   // node-minor tokens
    __shared__ __align__(16) float Bs[NPB][SS][KK];
    __shared__ __align__(16) float Cs[NPB][SS][KK];
    __shared__ __align__(16) float scp[DD][NPB];
    __shared__ float rbuf[NPB][4];
    __shared__ float gash[DD][NPB];    // gate linear result

    const int n0 = blockIdx.x * NPB;
    const int t = threadIdx.x;          // = column d

    // ---- build tokens (node-minor layout) ---------------------------------
#pragma unroll
    for (int m = 0; m < NPB; m++) {
        int n = n0 + m;
        tokp[0][t][m] = x[(size_t)n * DD + t];
#pragma unroll
        for (int s = 1; s < SS; s++)
            tokp[s][t][m] = g_seg[((size_t)(s - 1) * NN + n) * DD + t];
    }
    __syncthreads();

    // ---- delta projection + gate projection (merged), f32x2-packed --------
    ull accp[2][SS];
    ull ga01, ga23;
    {
        float bd = b_delta[t];
        ull bd2 = pack2(bd, bd);
#pragma unroll
        for (int s = 0; s < SS; s++) { accp[0][s] = bd2; accp[1][s] = bd2; }
        float bg = b_g[t];
        ga01 = ga23 = pack2(bg, bg);
    }
#pragma unroll 4
    for (int j = 0; j < DD; j++) {
        float w = W_delta[j * DD + t];
        float g = W_g[j * DD + t];
        ull w2 = pack2(w, w);
        ull g2 = pack2(g, g);
        ulonglong2 t0 = *(const ulonglong2*)&tokp[0][j][0];
        accp[0][0] = fma2(t0.x, w2, accp[0][0]);
        accp[1][0] = fma2(t0.y, w2, accp[1][0]);
        ga01 = fma2(t0.x, g2, ga01);
        ga23 = fma2(t0.y, g2, ga23);
#pragma unroll
        for (int s = 1; s < SS; s++) {
            ulonglong2 tv = *(const ulonglong2*)&tokp[s][j][0];
            accp[0][s] = fma2(tv.x, w2, accp[0][s]);
            accp[1][s] = fma2(tv.y, w2, accp[1][s]);
        }
    }
    float del[NPB][SS];
#pragma unroll
    for (int s = 0; s < SS; s++) {
        unpack2(accp[0][s], del[0][s], del[1][s]);
        unpack2(accp[1][s], del[2][s], del[3][s]);
    }
#pragma unroll
    for (int m = 0; m < NPB; m++)
#pragma unroll
        for (int s = 0; s < SS; s++)
            del[m][s] = softplus_fast(del[m][s]);
    {   // stash gate linear (pre-silu) in smem; applied after scan
        float g0, g1, g2v, g3;
        unpack2(ga01, g0, g1); unpack2(ga23, g2v, g3);
        gash[t][0] = g0; gash[t][1] = g1; gash[t][2] = g2v; gash[t][3] = g3;
    }

    // ---- merged B+C projection: 80 tasks, single round --------------------
    if (t < SS * KK) {
        int s = t / KK, k = t % KK;
        ull b01 = 0ull, b23 = 0ull, c01 = 0ull, c23 = 0ull;
#pragma unroll 4
        for (int j = 0; j < DD; j++) {
            float wb = W_B[j * KK + k];
            float wc = W_C[j * KK + k];
            ull wb2 = pack2(wb, wb);
            ull wc2 = pack2(wc, wc);
            ulonglong2 tv = *(const ulonglong2*)&tokp[s][j][0];
            b01 = fma2(tv.x, wb2, b01);
            b23 = fma2(tv.y, wb2, b23);
            c01 = fma2(tv.x, wc2, c01);
            c23 = fma2(tv.y, wc2, c23);
        }
        float v0, v1, v2, v3;
        unpack2(b01, v0, v1); unpack2(b23, v2, v3);
        Bs[0][s][k] = v0; Bs[1][s][k] = v1;
        Bs[2][s][k] = v2; Bs[3][s][k] = v3;
        unpack2(c01, v0, v1); unpack2(c23, v2, v3);
        Cs[0][s][k] = v0; Cs[1][s][k] = v1;
        Cs[2][s][k] = v2; Cs[3][s][k] = v3;
    }
    __syncthreads();

    // ---- single-pass bidirectional scan, k halves of 8, exp2-folded -------
    const int d = t;
    float ysb[NPB];
#pragma unroll
    for (int m = 0; m < NPB; m++) ysb[m] = 0.f;

#pragma unroll
    for (int half = 0; half < 2; half++) {
        float ac[8];
        {
            const float4* la = (const float4*)(log_A + d * KK + half * 8);
#pragma unroll
            for (int q = 0; q < 2; q++) {
                float4 v = la[q];
                ac[q * 4 + 0] = -LOG2E * __expf(v.x);
                ac[q * 4 + 1] = -LOG2E * __expf(v.y);
                ac[q * 4 + 2] = -LOG2E * __expf(v.z);
                ac[q * 4 + 3] = -LOG2E * __expf(v.w);
            }
        }
#pragma unroll
        for (int m = 0; m < NPB; m++) {
            float F[8], Dv[8], ap[8];
#pragma unroll
            for (int k = 0; k < 8; k++) { F[k] = 0.f; Dv[k] = 0.f; ap[k] = 0.f; }
            float ys = 0.f, yb = 0.f;
            const float4* Bp = (const float4*)&Bs[m][0][0];
            const float4* Cp = (const float4*)&Cs[m][0][0];
#pragma unroll
            for (int s = 0; s < SS; s++) {
                float dl = del[m][s];
                float dx = dl * tokp[s][d][m];
#pragma unroll
                for (int q = 0; q < 2; q++) {
                    float4 Bv = Bp[s * 4 + half * 2 + q];
                    float4 Cv = Cp[s * 4 + half * 2 + q];
#pragma unroll
                    for (int e = 0; e < 4; e++) {
                        int k = q * 4 + e;
                        float Be = (e == 0) ? Bv.x : (e == 1) ? Bv.y : (e == 2) ? Bv.z : Bv.w;
                        float Ce = (e == 0) ? Cv.x : (e == 1) ? Cv.y : (e == 2) ? Cv.z : Cv.w;
                        float a  = exp2f(dl * ac[k]);
                        float bx = dx * Be;
                        F[k]  = fmaf(a, F[k], bx);
                        ys    = fmaf(Ce, F[k], ys);
                        Dv[k] = fmaf(ap[k], Dv[k], Ce);
                        yb    = fmaf(bx, Dv[k], yb);
                        ap[k] = a;
                    }
                }
            }
            ysb[m] += ys + yb;
        }
    }
#pragma unroll
    for (int m = 0; m < NPB; m++)
        scp[d][m] = ysb[m] * (1.0f / SS);
    __syncthreads();

    // ---- out projection, f32x2-packed -------------------------------------
    ull oa01, oa23;
    {
        float bo = b_out[d];
        oa01 = oa23 = pack2(bo, bo);
    }
#pragma unroll 8
    for (int j = 0; j < DD; j++) {
        float o = W_out[j * DD + d];
        ull o2 = pack2(o, o);
        ulonglong2 sv = *(const ulonglong2*)&scp[j][0];
        oa01 = fma2(sv.x, o2, oa01);
        oa23 = fma2(sv.y, o2, oa23);
    }
    float res[NPB];
    {
        float oa[NPB];
        unpack2(oa01, oa[0], oa[1]); unpack2(oa23, oa[2], oa[3]);
#pragma unroll
        for (int m = 0; m < NPB; m++) {
            float gl = gash[d][m];
            float gate = gl / (1.0f + __expf(-gl));
            res[m] = tokp[0][d][m] + gate * oa[m];
        }
    }

    // ---- LayerNorm --------------------------------------------------------
    {
        float v[NPB];
#pragma unroll
        for (int m = 0; m < NPB; m++) v[m] = res[m];
#pragma unroll
        for (int o = 16; o; o >>= 1)
#pragma unroll
            for (int m = 0; m < NPB; m++)
                v[m] += __shfl_xor_sync(0xffffffffu, v[m], o);
        if ((t & 31) == 0)
#pragma unroll
            for (int m = 0; m < NPB; m++) rbuf[m][t >> 5] = v[m];
    }
    __syncthreads();
    float mean[NPB];
#pragma unroll
    for (int m = 0; m < NPB; m++)
        mean[m] = (rbuf[m][0] + rbuf[m][1] + rbuf[m][2] + rbuf[m][3]) * (1.0f / DD);
    __syncthreads();
    {
        float v[NPB];
#pragma unroll
        for (int m = 0; m < NPB; m++) {
            float c = res[m] - mean[m];
            v[m] = c * c;
        }
#pragma unroll
        for (int o = 16; o; o >>= 1)
#pragma unroll
            for (int m = 0; m < NPB; m++)
                v[m] += __shfl_xor_sync(0xffffffffu, v[m], o);
        if ((t & 31) == 0)
#pragma unroll
            for (int m = 0; m < NPB; m++) rbuf[m][t >> 5] = v[m];
    }
    __syncthreads();
    {
        float lg = ln_g[t], lb = ln_b[t];
#pragma unroll
        for (int m = 0; m < NPB; m++) {
            float var = (rbuf[m][0] + rbuf[m][1] + rbuf[m][2] + rbuf[m][3]) * (1.0f / DD);
            float c = res[m] - mean[m];
            out[(size_t)(n0 + m) * DD + t] = c * rsqrtf(var + LN_EPS) * lg + lb;
        }
    }
}

// ---------------------------------------------------------------------------
extern "C" void kernel_launch(void* const* d_in, const int* in_sizes, int n_in,
                              void* d_out, int out_size)
{
    const float* x          = (const float*)d_in[0];
    const int*   edge_index = (const int*)  d_in[1];
    const int*   edge_type  = (const int*)  d_in[2];
    const int*   perms      = (const int*)  d_in[3];
    const float* rel_table  = (const float*)d_in[4];
    const float* log_A      = (const float*)d_in[5];
    const float* W_B        = (const float*)d_in[6];
    const float* W_C        = (const float*)d_in[7];
    const float* W_delta    = (const float*)d_in[8];
    const float* b_delta    = (const float*)d_in[9];
    const float* W_g        = (const float*)d_in[10];
    const float* b_g        = (const float*)d_in[11];
    const float* W_out      = (const float*)d_in[12];
    const float* b_out      = (const float*)d_in[13];
    const float* ln_g       = (const float*)d_in[14];
    const float* ln_b       = (const float*)d_in[15];
    float* out = (float*)d_out;

    place_kernel<<<(NEDGE + 255) / 256, 256>>>(edge_index, edge_type, perms);
    gather_kernel<<<(NSEG * 32 + 255) / 256, 256>>>(x, rel_table);
    node_kernel<<<NN / NPB, BT>>>(x, log_A, W_B, W_C, W_delta, b_delta,
                                  W_g, b_g, W_out, b_out, ln_g, ln_b, out);
}